// round 7
// baseline (speedup 1.0000x reference)
#include <cuda_runtime.h>
#include <cstdint>
#include <cstddef>

#define B_   2048
#define T_   512
#define I_   58
#define H_   23
#define G_   69      // 3*H
#define ROWS_TOTAL (B_ * T_)          // 1048576
#define RPB  128                      // rows per block (xproj)

// scratch for x_proj, layout [b][t][g] == [row][g]  (+pad for clamped lanes)
__device__ float g_xp[(size_t)ROWS_TOTAL * G_ + 128];

// ---------- packed f32x2 helpers (Blackwell FFMA2) ----------
__device__ __forceinline__ unsigned long long fma2_(unsigned long long a,
                                                    unsigned long long b,
                                                    unsigned long long c) {
    unsigned long long d;
    asm("fma.rn.f32x2 %0, %1, %2, %3;" : "=l"(d) : "l"(a), "l"(b), "l"(c));
    return d;
}
__device__ __forceinline__ unsigned long long pack2_(float lo, float hi) {
    unsigned long long d;
    asm("mov.b64 %0, {%1, %2};"
        : "=l"(d) : "r"(__float_as_uint(lo)), "r"(__float_as_uint(hi)));
    return d;
}
__device__ __forceinline__ void unpack2_(unsigned long long v, float& lo, float& hi) {
    unsigned int ulo, uhi;
    asm("mov.b64 {%0, %1}, %2;" : "=r"(ulo), "=r"(uhi) : "l"(v));
    lo = __uint_as_float(ulo);
    hi = __uint_as_float(uhi);
}

// ---------- fast gate functions (MUFU-based, ~1e-6 rel err) ----------
__device__ __forceinline__ float sigmoidf_(float x) {
    return __fdividef(1.f, 1.f + __expf(-x));
}
__device__ __forceinline__ float tanhf_(float x) {
    return 1.f - __fdividef(2.f, __expf(2.f * x) + 1.f);
}

// =====================================================================
// Kernel 1: x_proj = task_seq @ W_ih^T + b_ih
// K-PAIR packed FFMA2: both operands native-layout LDS.64, no dup movs.
// 256 threads, 128 rows x 72(69) cols per block, 4x9 thread tile.
// Output staged in shared (union) then flushed with coalesced STG.128.
// =====================================================================
struct __align__(16) SmemU {
    union {
        struct {
            float xs[RPB * I_];        // [r][k]  29696 B  (verbatim copy of ts block)
            float ws[72 * I_];         // [g][k]  16704 B  (verbatim Wih, rows 69..71 = 0)
        } a;                            // 46400 B
        float os[RPB * G_];            // 35328 B
    };
};

__global__ void __launch_bounds__(256, 2) xproj_kernel(
    const float* __restrict__ ts,
    const float* __restrict__ Wih,
    const float* __restrict__ bih)
{
    __shared__ SmemU u;

    const int tid = threadIdx.x;
    const size_t row0 = (size_t)blockIdx.x * RPB;

    // W_ih verbatim ([g][k] is its native layout), zero-pad rows 69..71
    for (int i = tid; i < 72 * I_; i += 256)
        u.a.ws[i] = (i < G_ * I_) ? Wih[i] : 0.f;
    // task_seq block verbatim: contiguous 29696 B, 16B-aligned -> uint4 copy
    {
        const uint4* src = reinterpret_cast<const uint4*>(ts + row0 * I_);
        uint4* dst = reinterpret_cast<uint4*>(u.a.xs);
        for (int i = tid; i < (RPB * I_) / 4; i += 256)
            dst[i] = src[i];
    }
    __syncthreads();

    const int tx = tid & 7;          // 8 col groups of 9
    const int ty = tid >> 3;         // 32 row groups of 4
    const int rbase = ty * 4;
    const int gbase = tx * 9;

    unsigned long long acc[4][9];
    #pragma unroll
    for (int i = 0; i < 4; i++)
        #pragma unroll
        for (int c = 0; c < 9; c++)
            acc[i][c] = 0ull;

    const unsigned long long* xrow[4];
    #pragma unroll
    for (int i = 0; i < 4; i++)
        xrow[i] = reinterpret_cast<const unsigned long long*>(u.a.xs + (rbase + i) * I_);
    const unsigned long long* wrow[9];
    #pragma unroll
    for (int c = 0; c < 9; c++)
        wrow[c] = reinterpret_cast<const unsigned long long*>(u.a.ws + (gbase + c) * I_);

    for (int kp = 0; kp < I_ / 2; kp++) {         // 29 k-pairs
        unsigned long long xv[4], wv[9];
        #pragma unroll
        for (int i = 0; i < 4; i++) xv[i] = xrow[i][kp];
        #pragma unroll
        for (int c = 0; c < 9; c++) wv[c] = wrow[c][kp];
        #pragma unroll
        for (int i = 0; i < 4; i++)
            #pragma unroll
            for (int c = 0; c < 9; c++)
                acc[i][c] = fma2_(xv[i], wv[c], acc[i][c]);
    }

    float bv[9];
    #pragma unroll
    for (int c = 0; c < 9; c++) {
        int g = gbase + c;
        bv[c] = (g < G_) ? __ldg(&bih[g]) : 0.f;
    }

    __syncthreads();   // inputs consumed -> safe to overwrite union

    // Stage in shared, layout identical to global [r][g]
    #pragma unroll
    for (int i = 0; i < 4; i++) {
        int r = rbase + i;
        #pragma unroll
        for (int c = 0; c < 9; c++) {
            int g = gbase + c;
            if (g < G_) {
                float lo, hi;
                unpack2_(acc[i][c], lo, hi);
                u.os[r * G_ + g] = lo + hi + bv[c];
            }
        }
    }
    __syncthreads();

    // Coalesced flush: 128*69 floats = 2208 uint4
    const uint4* s4 = reinterpret_cast<const uint4*>(u.os);
    uint4* g4 = reinterpret_cast<uint4*>(g_xp + row0 * G_);
    for (int i = tid; i < (RPB * G_) / 4; i += 256)
        g4[i] = s4[i];
}

// =====================================================================
// Kernel 2: GRU scan. One warp per batch. All 32 lanes run the step
// body UNCONDITIONALLY (no divergent branch in the loop); indices
// clamped, pad h-slots forced to 0 via select, stores predicated.
// Double-buffered h -> ONE syncwarp per step. Bias pre-packed into
// the f32x2 accumulator init. x prefetched 2 steps ahead.
// =====================================================================
#define NW 7
#define SCAN_THREADS (NW * 32)

__global__ void __launch_bounds__(SCAN_THREADS, 2) gru_scan_kernel(
    const float* __restrict__ Whh,
    const float* __restrict__ bhh,
    const float* __restrict__ piw,
    const float* __restrict__ pib,
    float* __restrict__ out)
{
    __shared__ __align__(8) float hb[2][NW][32];

    const int warp = threadIdx.x >> 5;
    const int lane = threadIdx.x & 31;
    const int b    = blockIdx.x * NW + warp;
    const bool act = (lane < H_) && (b < B_);
    const int  j   = (lane < H_) ? lane : (H_ - 1);   // clamped gate index

    // k-packed W_hh rows (pad k=23 -> 0); clamped j keeps all loads in-bounds
    unsigned long long W2r[12], W2z[12], W2n[12];
    #pragma unroll
    for (int k2 = 0; k2 < 12; k2++) {
        int k = 2 * k2;
        float r1 = (k + 1 < H_) ? Whh[j * H_ + k + 1]            : 0.f;
        float z1 = (k + 1 < H_) ? Whh[(H_ + j) * H_ + k + 1]     : 0.f;
        float n1 = (k + 1 < H_) ? Whh[(2 * H_ + j) * H_ + k + 1] : 0.f;
        W2r[k2] = pack2_(Whh[j * H_ + k], r1);
        W2z[k2] = pack2_(Whh[(H_ + j) * H_ + k], z1);
        W2n[k2] = pack2_(Whh[(2 * H_ + j) * H_ + k], n1);
    }
    // bias pre-packed into accumulator init: (bias, 0)
    const unsigned long long b2r = pack2_(bhh[j], 0.f);
    const unsigned long long b2z = pack2_(bhh[H_ + j], 0.f);
    const unsigned long long b2n = pack2_(bhh[2 * H_ + j], 0.f);
    const float pw = piw[j], pb = pib[j];

    hb[0][warp][lane] = 0.f;
    hb[1][warp][lane] = 0.f;
    __syncwarp();

    const int bsafe = (b < B_) ? b : 0;
    const float* xp = g_xp + (size_t)bsafe * T_ * G_;
    float*       op = out  + (size_t)bsafe * T_ * H_ + j;

    float h = 0.f;
    // depth-2 prefetch (clamped j -> always in-bounds within the row)
    float x0r = xp[j],      x0z = xp[H_ + j],      x0n = xp[2 * H_ + j];
    float x1r = xp[G_ + j], x1z = xp[G_ + H_ + j], x1n = xp[G_ + 2 * H_ + j];

    int p = 0;
    #pragma unroll 2
    for (int t = 0; t < T_; t++) {
        // prefetch t+2 (pointer-select keeps it branchless & in-bounds)
        const float* q = (t + 2 < T_) ? (xp + 2 * G_) : xp;
        float x2r = q[j], x2z = q[H_ + j], x2n = q[2 * H_ + j];

        unsigned long long ar2 = b2r, az2 = b2z, an2 = b2n;
        const unsigned long long* h2 =
            reinterpret_cast<const unsigned long long*>(hb[p][warp]);
        #pragma unroll
        for (int k2 = 0; k2 < 12; k2++) {
            unsigned long long hv = h2[k2];      // broadcast LDS.64
            ar2 = fma2_(W2r[k2], hv, ar2);
            az2 = fma2_(W2z[k2], hv, az2);
            an2 = fma2_(W2n[k2], hv, an2);
        }
        float al, ah;
        unpack2_(ar2, al, ah); float ar = al + ah;
        unpack2_(az2, al, ah); float az = al + ah;
        unpack2_(an2, al, ah); float an = al + ah;

        float r = sigmoidf_(x0r + ar);
        float z = sigmoidf_(x0z + az);
        float n = tanhf_(fmaf(r, an, x0n));
        h = fmaf(z, h - n, n);                   // (1-z)*n + z*h

        hb[p ^ 1][warp][lane] = act ? h : 0.f;   // pad slots stay 0
        if (act) *op = fmaf(pw, h, pb);          // predicated STG, no branch
        __syncwarp();

        p ^= 1;
        x0r = x1r; x0z = x1z; x0n = x1n;
        x1r = x2r; x1z = x2z; x1n = x2n;
        xp += G_;
        op += H_;
    }

    if (act)
        out[(size_t)B_ * T_ * H_ + (size_t)b * H_ + lane] = h;   // hidden = hT
}

// =====================================================================
extern "C" void kernel_launch(void* const* d_in, const int* in_sizes, int n_in,
                              void* d_out, int out_size)
{
    const float* ts  = (const float*)d_in[0];  // task_seq (B,T,I)
    const float* Wih = (const float*)d_in[1];  // (69,58)
    const float* Whh = (const float*)d_in[2];  // (69,23)
    const float* bih = (const float*)d_in[3];  // (69,)
    const float* bhh = (const float*)d_in[4];  // (69,)
    const float* piw = (const float*)d_in[5];  // (23,)
    const float* pib = (const float*)d_in[6];  // (23,)
    float* out = (float*)d_out;

    xproj_kernel<<<ROWS_TOTAL / RPB, 256>>>(ts, Wih, bih);
    gru_scan_kernel<<<(B_ + NW - 1) / NW, SCAN_THREADS>>>(Whh, bhh, piw, pib, out);
}

// round 10
// speedup vs baseline: 1.1453x; 1.1453x over previous
#include <cuda_runtime.h>
#include <cstdint>
#include <cstddef>

#define B_   2048
#define T_   512
#define I_   58
#define H_   23
#define G_   69      // 3*H
#define ROWS_TOTAL (B_ * T_)          // 1048576

// scratch for x_proj, layout [b][t][g] == [row][g]  (+pad for clamped lanes)
__device__ float g_xp[(size_t)ROWS_TOTAL * G_ + 128];

// ---------- packed f32x2 helpers ----------
__device__ __forceinline__ unsigned long long fma2_(unsigned long long a,
                                                    unsigned long long b,
                                                    unsigned long long c) {
    unsigned long long d;
    asm("fma.rn.f32x2 %0, %1, %2, %3;" : "=l"(d) : "l"(a), "l"(b), "l"(c));
    return d;
}
__device__ __forceinline__ unsigned long long pack2_(float lo, float hi) {
    unsigned long long d;
    asm("mov.b64 %0, {%1, %2};"
        : "=l"(d) : "r"(__float_as_uint(lo)), "r"(__float_as_uint(hi)));
    return d;
}
__device__ __forceinline__ void unpack2_(unsigned long long v, float& lo, float& hi) {
    unsigned int ulo, uhi;
    asm("mov.b64 {%0, %1}, %2;" : "=r"(ulo), "=r"(uhi) : "l"(v));
    lo = __uint_as_float(ulo);
    hi = __uint_as_float(uhi);
}

// ---------- fast gate functions (MUFU-based, ~1e-6 rel err) ----------
__device__ __forceinline__ float sigmoidf_(float x) {
    return __fdividef(1.f, 1.f + __expf(-x));
}
__device__ __forceinline__ float tanhf_(float x) {
    return 1.f - __fdividef(2.f, __expf(2.f * x) + 1.f);
}

// ---------- tf32 helpers ----------
__device__ __forceinline__ unsigned int tf32_(float x) {
    unsigned int r;
    asm("cvt.rna.tf32.f32 %0, %1;" : "=r"(r) : "f"(x));
    return r;
}
__device__ __forceinline__ void mma_tf32_(float* d,
                                          unsigned a0, unsigned a1, unsigned a2, unsigned a3,
                                          unsigned b0, unsigned b1) {
    asm("mma.sync.aligned.m16n8k8.row.col.f32.tf32.tf32.f32 "
        "{%0,%1,%2,%3}, {%4,%5,%6,%7}, {%8,%9}, {%0,%1,%2,%3};"
        : "+f"(d[0]), "+f"(d[1]), "+f"(d[2]), "+f"(d[3])
        : "r"(a0), "r"(a1), "r"(a2), "r"(a3), "r"(b0), "r"(b1));
}

// =====================================================================
// Kernel 1: x_proj = task_seq @ W_ih^T + b_ih  via tf32 tensor cores.
// 3-term precision split: x = hi + lo (tf32), acc += hi*Whi + hi*Wlo +
// lo*Whi in fp32  ->  rel err ~1e-6.
// 256 threads = 8 warps x 16 rows = 128 rows/block. N padded 69->72
// (9 n-tiles of 8), K padded 58->64 (8 k-chunks of 8, predicated).
// A fragments loaded directly from gmem (no smem, no pipeline);
// W split hi/lo once into padded smem [72][68] (frag LDS bank = lane,
// conflict-free).
// =====================================================================
#define NP_ 72
#define WS_ 68   // padded k-stride for W smem

__global__ void __launch_bounds__(256) xproj_mma_kernel(
    const float* __restrict__ ts,
    const float* __restrict__ Wih,
    const float* __restrict__ bih)
{
    __shared__ unsigned int Whi[NP_][WS_];
    __shared__ unsigned int Wlo[NP_][WS_];
    __shared__ float bsh[NP_];

    const int tid = threadIdx.x;

    // zero-init (padding rows/cols must be 0)
    for (int i = tid; i < NP_ * WS_; i += 256) {
        (&Whi[0][0])[i] = 0u;
        (&Wlo[0][0])[i] = 0u;
    }
    for (int i = tid; i < NP_; i += 256)
        bsh[i] = (i < G_) ? bih[i] : 0.f;
    __syncthreads();

    // split W into tf32 hi/lo
    for (int i = tid; i < G_ * I_; i += 256) {
        int n = i / I_, k = i - n * I_;
        float w = Wih[i];
        unsigned int hi = tf32_(w);
        float lof = w - __uint_as_float(hi);
        Whi[n][k] = hi;
        Wlo[n][k] = tf32_(lof);
    }
    __syncthreads();

    const int warp = tid >> 5;
    const int lane = tid & 31;
    const int g    = lane >> 2;      // groupID 0..7
    const int tg   = lane & 3;       // thread-in-group 0..3

    const size_t row0 = (size_t)blockIdx.x * 128 + warp * 16;
    const float* A0 = ts + (row0 + g) * I_;        // rows for a0/a2
    const float* A1 = ts + (row0 + g + 8) * I_;    // rows for a1/a3

    float acc[9][4];
    #pragma unroll
    for (int n8 = 0; n8 < 9; n8++)
        #pragma unroll
        for (int c = 0; c < 4; c++)
            acc[n8][c] = 0.f;

    #pragma unroll
    for (int kc = 0; kc < 8; kc++) {
        const int c0 = kc * 8 + tg;
        const int c1 = c0 + 4;

        // A fragment (fp32 loads, predicated on k<58), then hi/lo split
        float x0 = (c0 < I_) ? A0[c0] : 0.f;   // a0: (row g,    col c0)
        float x1 = (c0 < I_) ? A1[c0] : 0.f;   // a1: (row g+8,  col c0)
        float x2 = (c1 < I_) ? A0[c1] : 0.f;   // a2: (row g,    col c1)
        float x3 = (c1 < I_) ? A1[c1] : 0.f;   // a3: (row g+8,  col c1)

        unsigned ah0 = tf32_(x0), ah1 = tf32_(x1), ah2 = tf32_(x2), ah3 = tf32_(x3);
        unsigned al0 = tf32_(x0 - __uint_as_float(ah0));
        unsigned al1 = tf32_(x1 - __uint_as_float(ah1));
        unsigned al2 = tf32_(x2 - __uint_as_float(ah2));
        unsigned al3 = tf32_(x3 - __uint_as_float(ah3));

        #pragma unroll
        for (int n8 = 0; n8 < 9; n8++) {
            const int nrow = n8 * 8 + g;
            unsigned bh0 = Whi[nrow][c0];   // B frag: (k=tg,   n=g)
            unsigned bh1 = Whi[nrow][c1];   //         (k=tg+4, n=g)
            unsigned bl0 = Wlo[nrow][c0];
            unsigned bl1 = Wlo[nrow][c1];
            mma_tf32_(acc[n8], ah0, ah1, ah2, ah3, bh0, bh1);  // hi*hi
            mma_tf32_(acc[n8], ah0, ah1, ah2, ah3, bl0, bl1);  // hi*lo
            mma_tf32_(acc[n8], al0, al1, al2, al3, bh0, bh1);  // lo*hi
        }
    }

    // epilogue: c0:(g, 2tg) c1:(g, 2tg+1) c2:(g+8, 2tg) c3:(g+8, 2tg+1)
    #pragma unroll
    for (int n8 = 0; n8 < 9; n8++) {
        #pragma unroll
        for (int c = 0; c < 4; c++) {
            int col = n8 * 8 + 2 * tg + (c & 1);
            if (col < G_) {
                size_t r = row0 + g + ((c >= 2) ? 8 : 0);
                g_xp[r * G_ + col] = acc[n8][c] + bsh[col];
            }
        }
    }
}

// =====================================================================
// Kernel 2: GRU scan (unchanged from best-known). One warp per batch,
// branchless body, double-buffered h, one syncwarp/step, depth-2 x
// prefetch, bias pre-packed into f32x2 accumulator init.
// =====================================================================
#define NW 7
#define SCAN_THREADS (NW * 32)

__global__ void __launch_bounds__(SCAN_THREADS, 2) gru_scan_kernel(
    const float* __restrict__ Whh,
    const float* __restrict__ bhh,
    const float* __restrict__ piw,
    const float* __restrict__ pib,
    float* __restrict__ out)
{
    __shared__ __align__(8) float hb[2][NW][32];

    const int warp = threadIdx.x >> 5;
    const int lane = threadIdx.x & 31;
    const int b    = blockIdx.x * NW + warp;
    const bool act = (lane < H_) && (b < B_);
    const int  j   = (lane < H_) ? lane : (H_ - 1);   // clamped gate index

    unsigned long long W2r[12], W2z[12], W2n[12];
    #pragma unroll
    for (int k2 = 0; k2 < 12; k2++) {
        int k = 2 * k2;
        float r1 = (k + 1 < H_) ? Whh[j * H_ + k + 1]            : 0.f;
        float z1 = (k + 1 < H_) ? Whh[(H_ + j) * H_ + k + 1]     : 0.f;
        float n1 = (k + 1 < H_) ? Whh[(2 * H_ + j) * H_ + k + 1] : 0.f;
        W2r[k2] = pack2_(Whh[j * H_ + k], r1);
        W2z[k2] = pack2_(Whh[(H_ + j) * H_ + k], z1);
        W2n[k2] = pack2_(Whh[(2 * H_ + j) * H_ + k], n1);
    }
    const unsigned long long b2r = pack2_(bhh[j], 0.f);
    const unsigned long long b2z = pack2_(bhh[H_ + j], 0.f);
    const unsigned long long b2n = pack2_(bhh[2 * H_ + j], 0.f);
    const float pw = piw[j], pb = pib[j];

    hb[0][warp][lane] = 0.f;
    hb[1][warp][lane] = 0.f;
    __syncwarp();

    const int bsafe = (b < B_) ? b : 0;
    const float* xp = g_xp + (size_t)bsafe * T_ * G_;
    float*       op = out  + (size_t)bsafe * T_ * H_ + j;

    float h = 0.f;
    float x0r = xp[j],      x0z = xp[H_ + j],      x0n = xp[2 * H_ + j];
    float x1r = xp[G_ + j], x1z = xp[G_ + H_ + j], x1n = xp[G_ + 2 * H_ + j];

    int p = 0;
    #pragma unroll 2
    for (int t = 0; t < T_; t++) {
        const float* q = (t + 2 < T_) ? (xp + 2 * G_) : xp;
        float x2r = q[j], x2z = q[H_ + j], x2n = q[2 * H_ + j];

        unsigned long long ar2 = b2r, az2 = b2z, an2 = b2n;
        const unsigned long long* h2 =
            reinterpret_cast<const unsigned long long*>(hb[p][warp]);
        #pragma unroll
        for (int k2 = 0; k2 < 12; k2++) {
            unsigned long long hv = h2[k2];      // broadcast LDS.64
            ar2 = fma2_(W2r[k2], hv, ar2);
            az2 = fma2_(W2z[k2], hv, az2);
            an2 = fma2_(W2n[k2], hv, an2);
        }
        float al, ah;
        unpack2_(ar2, al, ah); float ar = al + ah;
        unpack2_(az2, al, ah); float az = al + ah;
        unpack2_(an2, al, ah); float an = al + ah;

        float r = sigmoidf_(x0r + ar);
        float z = sigmoidf_(x0z + az);
        float n = tanhf_(fmaf(r, an, x0n));
        h = fmaf(z, h - n, n);                   // (1-z)*n + z*h

        hb[p ^ 1][warp][lane] = act ? h : 0.f;
        if (act) *op = fmaf(pw, h, pb);
        __syncwarp();

        p ^= 1;
        x0r = x1r; x0z = x1z; x0n = x1n;
        x1r = x2r; x1z = x2z; x1n = x2n;
        xp += G_;
        op += H_;
    }

    if (act)
        out[(size_t)B_ * T_ * H_ + (size_t)b * H_ + lane] = h;   // hidden = hT
}

// =====================================================================
extern "C" void kernel_launch(void* const* d_in, const int* in_sizes, int n_in,
                              void* d_out, int out_size)
{
    const float* ts  = (const float*)d_in[0];  // task_seq (B,T,I)
    const float* Wih = (const float*)d_in[1];  // (69,58)
    const float* Whh = (const float*)d_in[2];  // (69,23)
    const float* bih = (const float*)d_in[3];  // (69,)
    const float* bhh = (const float*)d_in[4];  // (69,)
    const float* piw = (const float*)d_in[5];  // (23,)
    const float* pib = (const float*)d_in[6];  // (23,)
    float* out = (float*)d_out;

    xproj_mma_kernel<<<ROWS_TOTAL / 128, 256>>>(ts, Wih, bih);
    gru_scan_kernel<<<(B_ + NW - 1) / NW, SCAN_THREADS>>>(Whh, bhh, piw, pib, out);
}